// round 3
// baseline (speedup 1.0000x reference)
#include <cuda_runtime.h>

#define THREADS 512
#define DEPTHN  4096
#define NROWS   8192
#define KINV    0.70710678118654752440f

// Dynamic smem layout (float indices):
//  s_vb [0,4096)      broadcast vector b
//  s_vs [4096,8192)   output scale vector s
//  A    [8192,12288)  wavedec coefficients c = [cA4|cD4|cD3|cD2|cD1]
//  B    [12288,16384) permuted+gained coefficients d
// Total 16384 floats = 64 KB. perm and vec_g live in registers (row-invariant).

__global__ void __launch_bounds__(THREADS, 2)
wavelet_kernel(const float* __restrict__ x,
               const float* __restrict__ vb,
               const float* __restrict__ vg,
               const float* __restrict__ vs,
               const int*   __restrict__ perm,
               float*       __restrict__ out)
{
    extern __shared__ float sm[];
    float* s_vb = sm;
    float* s_vs = sm + 4096;
    float* A    = sm + 8192;
    float* Bf   = sm + 12288;

    const int t = threadIdx.x;

    // ---- row-invariant params into registers (coalesced, once per CTA) ----
    int   pr[8];
    float gr[8];
    #pragma unroll
    for (int m = 0; m < 8; m++) {
        pr[m] = perm[t + m * THREADS];
        gr[m] = vg[t + m * THREADS];
    }
    // ---- vb, vs into smem ----
    {
        const float4* vb4 = (const float4*)vb;
        const float4* vs4 = (const float4*)vs;
        ((float4*)s_vb)[2 * t]     = vb4[2 * t];
        ((float4*)s_vb)[2 * t + 1] = vb4[2 * t + 1];
        ((float4*)s_vs)[2 * t]     = vs4[2 * t];
        ((float4*)s_vs)[2 * t + 1] = vs4[2 * t + 1];
    }
    __syncthreads();

    int row = blockIdx.x;
    const int stride = gridDim.x;

    // prefetch first row (8 floats / thread); gridDim.x << NROWS so always valid
    float4 r0, r1;
    {
        const float4* xr = (const float4*)(x + (size_t)row * DEPTHN);
        r0 = xr[2 * t];
        r1 = xr[2 * t + 1];
    }

    for (; row < NROWS; row += stride) {
        // ========= STEP 1: y = x*vb + full 4-level Haar analysis, in registers ====
        // thread t owns y[8t..8t+7]; c layout: [cA4:0 | cD4:256 | cD3:512 | cD2:1024 | cD1:2048]
        {
            float4 b0 = ((const float4*)s_vb)[2 * t];
            float4 b1 = ((const float4*)s_vb)[2 * t + 1];
            float y0 = r0.x * b0.x, y1 = r0.y * b0.y, y2 = r0.z * b0.z, y3 = r0.w * b0.w;
            float y4 = r1.x * b1.x, y5 = r1.y * b1.y, y6 = r1.z * b1.z, y7 = r1.w * b1.w;

            // scale 1: cD1[4t..4t+3]
            float a10 = (y0 + y1) * KINV, d10 = (y0 - y1) * KINV;
            float a11 = (y2 + y3) * KINV, d11 = (y2 - y3) * KINV;
            float a12 = (y4 + y5) * KINV, d12 = (y4 - y5) * KINV;
            float a13 = (y6 + y7) * KINV, d13 = (y6 - y7) * KINV;
            ((float4*)(A + 2048))[t] = make_float4(d10, d11, d12, d13);

            // prefetch next row: DRAM latency hidden behind permute + synthesis
            {
                int nrow = row + stride;
                if (nrow < NROWS) {
                    const float4* xr = (const float4*)(x + (size_t)nrow * DEPTHN);
                    r0 = xr[2 * t];
                    r1 = xr[2 * t + 1];
                }
            }

            // scale 2: cD2[2t..2t+1]
            float a20 = (a10 + a11) * KINV, d20 = (a10 - a11) * KINV;
            float a21 = (a12 + a13) * KINV, d21 = (a12 - a13) * KINV;
            ((float2*)(A + 1024))[t] = make_float2(d20, d21);

            // scale 3: cD3[t]
            float a3v = (a20 + a21) * KINV;
            A[512 + t] = (a20 - a21) * KINV;

            // scale 4 via shfl: pair (2j,2j+1) = threads (t, t^1)
            float prt = __shfl_xor_sync(0xffffffffu, a3v, 1);
            if ((t & 1) == 0) {
                int j = t >> 1;
                A[j]       = (a3v + prt) * KINV;   // cA4[j]
                A[256 + j] = (a3v - prt) * KINV;   // cD4[j]
            }
        }
        __syncthreads();

        // ========= STEP 2: permute + gain from registers: d[j] = c[perm[j]]*g[j] ==
        #pragma unroll
        for (int m = 0; m < 8; m++)
            Bf[t + m * THREADS] = A[pr[m]] * gr[m];
        __syncthreads();

        // ========= STEP 3: full 4-level synthesis, all 512 threads ================
        // Reference slices: coeff_lst = [d[0:256], d[2048:2304], d[1024:1536],
        //                                d[512:1536], d[256:2304]]
        // thread t reconstructs outputs [8t..8t+7]
        {
            int   h  = t >> 1;
            float a0 = Bf[h];               // broadcast pair-read (free)
            float c4 = Bf[2048 + h];
            float a1 = ((t & 1) ? (a0 - c4) : (a0 + c4)) * KINV;   // level-1 recon, pos t

            float c3   = Bf[1024 + t];
            float a2_0 = (a1 + c3) * KINV;
            float a2_1 = (a1 - c3) * KINV;

            float2 c2   = ((const float2*)(Bf + 512))[t];
            float  a3_0 = (a2_0 + c2.x) * KINV;
            float  a3_1 = (a2_0 - c2.x) * KINV;
            float  a3_2 = (a2_1 + c2.y) * KINV;
            float  a3_3 = (a2_1 - c2.y) * KINV;

            float4 c1 = ((const float4*)(Bf + 256))[t];   // d[256+4t .. +3]
            float4 v0 = ((const float4*)s_vs)[2 * t];
            float4 v1 = ((const float4*)s_vs)[2 * t + 1];

            float4 o0, o1;
            o0.x = ((a3_0 + c1.x) * KINV) * v0.x;
            o0.y = ((a3_0 - c1.x) * KINV) * v0.y;
            o0.z = ((a3_1 + c1.y) * KINV) * v0.z;
            o0.w = ((a3_1 - c1.y) * KINV) * v0.w;
            o1.x = ((a3_2 + c1.z) * KINV) * v1.x;
            o1.y = ((a3_2 - c1.z) * KINV) * v1.y;
            o1.z = ((a3_3 + c1.w) * KINV) * v1.z;
            o1.w = ((a3_3 - c1.w) * KINV) * v1.w;

            float4* orow = (float4*)(out + (size_t)row * DEPTHN);
            orow[2 * t]     = o0;
            orow[2 * t + 1] = o1;
        }
        // No trailing barrier: next iteration's step-1 __syncthreads orders these
        // Bf reads against the next step-2 Bf writes; step 1 itself only writes A,
        // which step 3 never touches.
    }
}

extern "C" void kernel_launch(void* const* d_in, const int* in_sizes, int n_in,
                              void* d_out, int out_size)
{
    const float* x    = (const float*)d_in[0];
    const float* vb   = (const float*)d_in[1];
    const float* vg   = (const float*)d_in[2];
    const float* vs   = (const float*)d_in[3];
    const int*   perm = (const int*)d_in[4];
    float*       out  = (float*)d_out;

    const size_t smem_bytes = 16384 * sizeof(float);   // 64 KB
    cudaFuncSetAttribute(wavelet_kernel,
                         cudaFuncAttributeMaxDynamicSharedMemorySize,
                         (int)smem_bytes);

    // 296 = 2 CTAs/SM on 148 SMs: one resident wave, params cached once,
    // each CTA sweeps ~28 rows with a software-pipelined row prefetch.
    wavelet_kernel<<<296, THREADS, smem_bytes>>>(x, vb, vg, vs, perm, out);
}

// round 4
// speedup vs baseline: 1.1028x; 1.1028x over previous
#include <cuda_runtime.h>

#define THREADS 512
#define DEPTHN  4096
#define NROWS   8192
#define KINV    0.70710678118654752440f

// Dynamic smem layout (float indices):
//  s_vb [0,4096)       broadcast vector b
//  s_vs [4096,8192)    output scale vector s
//  A0   [8192,12288)   wavedec coeffs, ping
//  A1   [12288,16384)  wavedec coeffs, pong
// Total 64 KB. perm/vec_g live entirely in registers (row-invariant, per-thread
// slots for exactly the 9 positions this thread's synthesis needs).

__global__ void __launch_bounds__(THREADS, 2)
wavelet_kernel(const float* __restrict__ x,
               const float* __restrict__ vb,
               const float* __restrict__ vg,
               const float* __restrict__ vs,
               const int*   __restrict__ perm,
               float*       __restrict__ out)
{
    extern __shared__ float sm[];
    float* s_vb = sm;
    float* s_vs = sm + 4096;
    float* A0   = sm + 8192;
    float* A1   = sm + 12288;

    const int t = threadIdx.x;
    const int h = t >> 1;

    // ---- row-invariant permutation/gain slots for THIS thread's synthesis ----
    // Reference slices: coeff_lst = [d[0:256], d[2048:2304], d[1024:1536],
    //                                d[512:1536], d[256:2304]],  d[j]=c[perm[j]]*g[j]
    int   p0 = perm[h],            p1 = perm[2048 + h];
    int   p2 = perm[1024 + t];
    int   p3 = perm[512 + 2 * t],  p4 = perm[512 + 2 * t + 1];
    int   p5 = perm[256 + 4 * t],     p6 = perm[256 + 4 * t + 1];
    int   p7 = perm[256 + 4 * t + 2], p8 = perm[256 + 4 * t + 3];
    float g0 = vg[h],              g1 = vg[2048 + h];
    float g2 = vg[1024 + t];
    float g3 = vg[512 + 2 * t],    g4 = vg[512 + 2 * t + 1];
    float g5 = vg[256 + 4 * t],       g6 = vg[256 + 4 * t + 1];
    float g7 = vg[256 + 4 * t + 2],   g8 = vg[256 + 4 * t + 3];

    // ---- vb, vs cached in smem (conflict-free float4 reads per row) ----
    {
        const float4* vb4 = (const float4*)vb;
        const float4* vs4 = (const float4*)vs;
        ((float4*)s_vb)[2 * t]     = vb4[2 * t];
        ((float4*)s_vb)[2 * t + 1] = vb4[2 * t + 1];
        ((float4*)s_vs)[2 * t]     = vs4[2 * t];
        ((float4*)s_vs)[2 * t + 1] = vs4[2 * t + 1];
    }
    __syncthreads();

    int row = blockIdx.x;
    const int stride = gridDim.x;

    // prefetch first row (8 floats / thread)
    float4 r0, r1;
    {
        const float4* xr = (const float4*)(x + (size_t)row * DEPTHN);
        r0 = xr[2 * t];
        r1 = xr[2 * t + 1];
    }

    float* Acur = A0;
    float* Anxt = A1;

    for (; row < NROWS; row += stride) {
        // ===== STEP 1: y = x*vb + full 4-level Haar analysis (registers) =========
        // c layout in Acur: [cA4:0 | cD4:256 | cD3:512 | cD2:1024 | cD1:2048]
        {
            float4 b0 = ((const float4*)s_vb)[2 * t];
            float4 b1 = ((const float4*)s_vb)[2 * t + 1];
            float y0 = r0.x * b0.x, y1 = r0.y * b0.y, y2 = r0.z * b0.z, y3 = r0.w * b0.w;
            float y4 = r1.x * b1.x, y5 = r1.y * b1.y, y6 = r1.z * b1.z, y7 = r1.w * b1.w;

            float a10 = (y0 + y1) * KINV, d10 = (y0 - y1) * KINV;
            float a11 = (y2 + y3) * KINV, d11 = (y2 - y3) * KINV;
            float a12 = (y4 + y5) * KINV, d12 = (y4 - y5) * KINV;
            float a13 = (y6 + y7) * KINV, d13 = (y6 - y7) * KINV;
            ((float4*)(Acur + 2048))[t] = make_float4(d10, d11, d12, d13);

            // prefetch next row — DRAM latency overlaps synthesis below
            {
                int nrow = row + stride;
                if (nrow < NROWS) {
                    const float4* xr = (const float4*)(x + (size_t)nrow * DEPTHN);
                    r0 = xr[2 * t];
                    r1 = xr[2 * t + 1];
                }
            }

            float a20 = (a10 + a11) * KINV, d20 = (a10 - a11) * KINV;
            float a21 = (a12 + a13) * KINV, d21 = (a12 - a13) * KINV;
            ((float2*)(Acur + 1024))[t] = make_float2(d20, d21);

            float a3v = (a20 + a21) * KINV;
            Acur[512 + t] = (a20 - a21) * KINV;

            float prt = __shfl_xor_sync(0xffffffffu, a3v, 1);
            if ((t & 1) == 0) {
                Acur[h]       = (a3v + prt) * KINV;   // cA4
                Acur[256 + h] = (a3v - prt) * KINV;   // cD4
            }
        }
        __syncthreads();   // the ONLY barrier per row (ping-pong makes it safe)

        // ===== STEP 2+3 fused: gather permuted coeffs from Acur, synthesize ======
        // thread t reconstructs outputs [8t..8t+7]
        {
            float dA = Acur[p0] * g0;                 // pair-broadcast (t, t^1 share p0)
            float dD = Acur[p1] * g1;
            float a1 = ((t & 1) ? (dA - dD) : (dA + dD)) * KINV;

            float d2   = Acur[p2] * g2;
            float a2_0 = (a1 + d2) * KINV;
            float a2_1 = (a1 - d2) * KINV;

            float d3 = Acur[p3] * g3;
            float d4 = Acur[p4] * g4;
            float a3_0 = (a2_0 + d3) * KINV;
            float a3_1 = (a2_0 - d3) * KINV;
            float a3_2 = (a2_1 + d4) * KINV;
            float a3_3 = (a2_1 - d4) * KINV;

            float d5 = Acur[p5] * g5;
            float d6 = Acur[p6] * g6;
            float d7 = Acur[p7] * g7;
            float d8 = Acur[p8] * g8;

            float4 v0 = ((const float4*)s_vs)[2 * t];
            float4 v1 = ((const float4*)s_vs)[2 * t + 1];

            float4 o0, o1;
            o0.x = ((a3_0 + d5) * KINV) * v0.x;
            o0.y = ((a3_0 - d5) * KINV) * v0.y;
            o0.z = ((a3_1 + d6) * KINV) * v0.z;
            o0.w = ((a3_1 - d6) * KINV) * v0.w;
            o1.x = ((a3_2 + d7) * KINV) * v1.x;
            o1.y = ((a3_2 - d7) * KINV) * v1.y;
            o1.z = ((a3_3 + d8) * KINV) * v1.z;
            o1.w = ((a3_3 - d8) * KINV) * v1.w;

            float4* orow = (float4*)(out + (size_t)row * DEPTHN);
            orow[2 * t]     = o0;
            orow[2 * t + 1] = o1;
        }

        // swap ping-pong: next iteration writes the other buffer, so this
        // iteration's reads of Acur are protected by the next barrier.
        float* tmp = Acur; Acur = Anxt; Anxt = tmp;
    }
}

extern "C" void kernel_launch(void* const* d_in, const int* in_sizes, int n_in,
                              void* d_out, int out_size)
{
    const float* x    = (const float*)d_in[0];
    const float* vb   = (const float*)d_in[1];
    const float* vg   = (const float*)d_in[2];
    const float* vs   = (const float*)d_in[3];
    const int*   perm = (const int*)d_in[4];
    float*       out  = (float*)d_out;

    const size_t smem_bytes = 16384 * sizeof(float);   // 64 KB
    cudaFuncSetAttribute(wavelet_kernel,
                         cudaFuncAttributeMaxDynamicSharedMemorySize,
                         (int)smem_bytes);

    // 296 = 2 CTAs/SM on 148 SMs: one resident wave, each CTA sweeps ~28 rows,
    // 1 barrier per row, software-pipelined row prefetch.
    wavelet_kernel<<<296, THREADS, smem_bytes>>>(x, vb, vg, vs, perm, out);
}

// round 9
// speedup vs baseline: 1.1109x; 1.0073x over previous
#include <cuda_runtime.h>

#define THREADS 512
#define DEPTHN  4096
#define NROWS   8192

// Dynamic smem: A0 [0,4096), A1 [4096,8192) — raw wavedec coeff ping-pong, 32 KB.
// ALL parameters (vb, vs, perm slots, folded gains) live in registers:
// row-invariant, thread-local. 1 CTA/SM so the ~80-reg footprint fits.

__global__ void __launch_bounds__(THREADS, 1)
wavelet_kernel(const float* __restrict__ x,
               const float* __restrict__ vb,
               const float* __restrict__ vg,
               const float* __restrict__ vs,
               const int*   __restrict__ perm,
               float*       __restrict__ out)
{
    extern __shared__ float sm[];
    float* A0 = sm;
    float* A1 = sm + 4096;

    const int t = threadIdx.x;
    const int h = t >> 1;

    // ---- folded gains -------------------------------------------------------
    // Analysis stores RAW sums/differences. True coeff = raw * K^region:
    //   region(p): [0,512)->K^4  [512,1024)->K^3  [1024,2048)->K^2  [2048,4096)->K^1
    // Synthesis is RAW adds; true output needs K^dest per leaf:
    //   slots 0,1 -> K^4   slot 2 -> K^3   slots 3,4 -> K^2   slots 5..8 -> K^1
    // g'[slot] = g * K^(region(p)+dest). Exact by linearity.
    const float KP[9] = {1.f,
                         0.70710678118654752440f,   // K^1
                         0.5f,                      // K^2
                         0.35355339059327376220f,   // K^3
                         0.25f,                     // K^4
                         0.17677669529663688110f,   // K^5
                         0.125f,                    // K^6
                         0.08838834764831844055f,   // K^7
                         0.0625f};                  // K^8

    // Reference slices: coeff_lst = [d[0:256], d[2048:2304], d[1024:1536],
    //                                d[512:1536], d[256:2304]],  d[j]=c[perm[j]]*g[j]
    int ji[9];
    ji[0] = h;              ji[1] = 2048 + h;
    ji[2] = 1024 + t;
    ji[3] = 512 + 2 * t;    ji[4] = 512 + 2 * t + 1;
    ji[5] = 256 + 4 * t;    ji[6] = 256 + 4 * t + 1;
    ji[7] = 256 + 4 * t + 2;
    ji[8] = 256 + 4 * t + 3;
    const int dest[9] = {4, 4, 3, 2, 2, 1, 1, 1, 1};

    int   p[9];
    float g[9];
    #pragma unroll
    for (int s = 0; s < 9; s++) {
        int pi = perm[ji[s]];
        p[s] = pi;
        int reg = (pi < 512) ? 4 : (pi < 1024) ? 3 : (pi < 2048) ? 2 : 1;
        g[s] = vg[ji[s]] * KP[reg + dest[s]];
    }
    // fold the level-1 synthesis sign into g[1]: odd threads subtract dD.
    if (t & 1) g[1] = -g[1];

    // ---- vb, vs in registers (row-invariant, thread-local slots) ------------
    float4 b0 = ((const float4*)vb)[2 * t];
    float4 b1 = ((const float4*)vb)[2 * t + 1];
    float4 v0 = ((const float4*)vs)[2 * t];
    float4 v1 = ((const float4*)vs)[2 * t + 1];

    int row = blockIdx.x;
    const int stride = gridDim.x;

    // prefetch first row
    float4 r0, r1;
    {
        const float4* xr = (const float4*)(x + (size_t)row * DEPTHN);
        r0 = xr[2 * t];
        r1 = xr[2 * t + 1];
    }

    float* Acur = A0;
    float* Anxt = A1;
    float4* orow = (float4*)(out + (size_t)row * DEPTHN);
    const size_t ostride = (size_t)stride * (DEPTHN / 4);

    #pragma unroll 1
    for (; row < NROWS; row += stride) {
        // ===== STEP 1: y = x*vb, RAW 4-level Haar analysis (adds only) =========
        // Acur layout: [rawA4:0 | rawD4:256 | rawD3:512 | rawD2:1024 | rawD1:2048]
        {
            float y0 = r0.x * b0.x, y1 = r0.y * b0.y, y2 = r0.z * b0.z, y3 = r0.w * b0.w;
            float y4 = r1.x * b1.x, y5 = r1.y * b1.y, y6 = r1.z * b1.z, y7 = r1.w * b1.w;

            float a10 = y0 + y1, d10 = y0 - y1;
            float a11 = y2 + y3, d11 = y2 - y3;
            float a12 = y4 + y5, d12 = y4 - y5;
            float a13 = y6 + y7, d13 = y6 - y7;
            ((float4*)(Acur + 2048))[t] = make_float4(d10, d11, d12, d13);

            // prefetch next row — DRAM latency overlaps synthesis below
            {
                int nrow = row + stride;
                if (nrow < NROWS) {
                    const float4* xr = (const float4*)(x + (size_t)nrow * DEPTHN);
                    r0 = xr[2 * t];
                    r1 = xr[2 * t + 1];
                }
            }

            float a20 = a10 + a11, d20 = a10 - a11;
            float a21 = a12 + a13, d21 = a12 - a13;
            ((float2*)(Acur + 1024))[t] = make_float2(d20, d21);

            float a3v = a20 + a21;
            Acur[512 + t] = a20 - a21;

            float prt = __shfl_xor_sync(0xffffffffu, a3v, 1);
            if ((t & 1) == 0) {
                Acur[h]       = a3v + prt;   // rawA4
                Acur[256 + h] = a3v - prt;   // rawD4
            }
        }
        __syncthreads();   // only barrier per row (ping-pong protects reads)

        // ===== STEP 2+3 fused: gather + RAW synthesis + final vs scale =========
        // thread t reconstructs outputs [8t..8t+7]
        {
            float a1 = Acur[p[0]] * g[0];          // pair-broadcast reads
            a1 = fmaf(Acur[p[1]], g[1], a1);       // sign pre-folded into g[1]

            float d2   = Acur[p[2]] * g[2];
            float a2_0 = a1 + d2;
            float a2_1 = a1 - d2;

            float d3 = Acur[p[3]] * g[3];
            float d4 = Acur[p[4]] * g[4];
            float a3_0 = a2_0 + d3;
            float a3_1 = a2_0 - d3;
            float a3_2 = a2_1 + d4;
            float a3_3 = a2_1 - d4;

            float d5 = Acur[p[5]] * g[5];
            float d6 = Acur[p[6]] * g[6];
            float d7 = Acur[p[7]] * g[7];
            float d8 = Acur[p[8]] * g[8];

            float4 o0, o1;
            o0.x = (a3_0 + d5) * v0.x;
            o0.y = (a3_0 - d5) * v0.y;
            o0.z = (a3_1 + d6) * v0.z;
            o0.w = (a3_1 - d6) * v0.w;
            o1.x = (a3_2 + d7) * v1.x;
            o1.y = (a3_2 - d7) * v1.y;
            o1.z = (a3_3 + d8) * v1.z;
            o1.w = (a3_3 - d8) * v1.w;

            orow[2 * t]     = o0;
            orow[2 * t + 1] = o1;
        }

        orow += ostride;
        float* tmp = Acur; Acur = Anxt; Anxt = tmp;
    }
}

extern "C" void kernel_launch(void* const* d_in, const int* in_sizes, int n_in,
                              void* d_out, int out_size)
{
    const float* x    = (const float*)d_in[0];
    const float* vb   = (const float*)d_in[1];
    const float* vg   = (const float*)d_in[2];
    const float* vs   = (const float*)d_in[3];
    const int*   perm = (const int*)d_in[4];
    float*       out  = (float*)d_out;

    const size_t smem_bytes = 8192 * sizeof(float);   // 32 KB
    cudaFuncSetAttribute(wavelet_kernel,
                         cudaFuncAttributeMaxDynamicSharedMemorySize,
                         (int)smem_bytes);

    // 148 CTAs = 1/SM; all params in registers, ~55 rows per CTA,
    // 1 barrier per row, software-pipelined row prefetch.
    wavelet_kernel<<<148, THREADS, smem_bytes>>>(x, vb, vg, vs, perm, out);
}

// round 10
// speedup vs baseline: 1.1351x; 1.0218x over previous
#include <cuda_runtime.h>

#define THREADS 512
#define DEPTHN  4096
#define NROWS   8192
#define NPAIRS  (NROWS / 2)

// Dynamic smem: four 4096-float coeff buffers (64 KB), ping-pong by PAIR:
//   pair-iteration k uses buffers [sel*2], [sel*2+1]; sel toggles per iteration.
// One __syncthreads per PAIR (0.5 per row): iter-k reads finish before iter-k+2
// rewrites the same pair, ordered by iter-k+1's barrier.
// ALL parameters (vb, vs, perm slots, folded gains) live in registers.

__global__ void __launch_bounds__(THREADS, 1)
wavelet_kernel(const float* __restrict__ x,
               const float* __restrict__ vb,
               const float* __restrict__ vg,
               const float* __restrict__ vs,
               const int*   __restrict__ perm,
               float*       __restrict__ out)
{
    extern __shared__ float sm[];

    const int t = threadIdx.x;
    const int h = t >> 1;

    // ---- folded gains (exact by linearity; see R4-R9 derivation) ------------
    // raw analysis coeff * K^region(src) ; synthesis leaf needs K^dest
    const float KP[9] = {1.f,
                         0.70710678118654752440f,
                         0.5f,
                         0.35355339059327376220f,
                         0.25f,
                         0.17677669529663688110f,
                         0.125f,
                         0.08838834764831844055f,
                         0.0625f};

    // coeff_lst = [d[0:256], d[2048:2304], d[1024:1536], d[512:1536], d[256:2304]]
    int ji[9];
    ji[0] = h;              ji[1] = 2048 + h;
    ji[2] = 1024 + t;
    ji[3] = 512 + 2 * t;    ji[4] = 512 + 2 * t + 1;
    ji[5] = 256 + 4 * t;    ji[6] = 256 + 4 * t + 1;
    ji[7] = 256 + 4 * t + 2;
    ji[8] = 256 + 4 * t + 3;
    const int dest[9] = {4, 4, 3, 2, 2, 1, 1, 1, 1};

    int   p[9];
    float g[9];
    #pragma unroll
    for (int s = 0; s < 9; s++) {
        int pi = perm[ji[s]];
        p[s] = pi;
        int reg = (pi < 512) ? 4 : (pi < 1024) ? 3 : (pi < 2048) ? 2 : 1;
        g[s] = vg[ji[s]] * KP[reg + dest[s]];
    }
    if (t & 1) g[1] = -g[1];   // fold level-1 synthesis sign

    // ---- vb, vs in registers ------------------------------------------------
    float4 b0 = ((const float4*)vb)[2 * t];
    float4 b1 = ((const float4*)vb)[2 * t + 1];
    float4 v0 = ((const float4*)vs)[2 * t];
    float4 v1 = ((const float4*)vs)[2 * t + 1];

    int pr = blockIdx.x;
    const int stride = gridDim.x;

    // prefetch first pair: rows 2pr (r0,r1) and 2pr+1 (r2,r3)
    float4 r0, r1, r2, r3;
    {
        const float4* xr = (const float4*)(x + (size_t)(2 * pr) * DEPTHN);
        r0 = xr[2 * t];
        r1 = xr[2 * t + 1];
        r2 = xr[1024 + 2 * t];
        r3 = xr[1024 + 2 * t + 1];
    }

    int sel = 0;

    #pragma unroll 1
    for (; pr < NPAIRS; pr += stride) {
        float* Aa = sm + sel * 8192;        // row 2pr coeffs
        float* Ab = Aa + 4096;              // row 2pr+1 coeffs
        const int npr = pr + stride;
        const float4* xn = (const float4*)(x + (size_t)(2 * npr) * DEPTHN);

        // ===== analysis row A (consumes r0,r1) + immediate prefetch ==========
        {
            float y0 = r0.x * b0.x, y1 = r0.y * b0.y, y2 = r0.z * b0.z, y3 = r0.w * b0.w;
            float y4 = r1.x * b1.x, y5 = r1.y * b1.y, y6 = r1.z * b1.z, y7 = r1.w * b1.w;
            if (npr < NPAIRS) { r0 = xn[2 * t]; r1 = xn[2 * t + 1]; }

            float a10 = y0 + y1, d10 = y0 - y1;
            float a11 = y2 + y3, d11 = y2 - y3;
            float a12 = y4 + y5, d12 = y4 - y5;
            float a13 = y6 + y7, d13 = y6 - y7;
            ((float4*)(Aa + 2048))[t] = make_float4(d10, d11, d12, d13);

            float a20 = a10 + a11, d20 = a10 - a11;
            float a21 = a12 + a13, d21 = a12 - a13;
            ((float2*)(Aa + 1024))[t] = make_float2(d20, d21);

            float a3v = a20 + a21;
            Aa[512 + t] = a20 - a21;

            float prt = __shfl_xor_sync(0xffffffffu, a3v, 1);
            if ((t & 1) == 0) {
                Aa[h]       = a3v + prt;
                Aa[256 + h] = a3v - prt;
            }
        }

        // ===== analysis row B (consumes r2,r3) + immediate prefetch ==========
        {
            float y0 = r2.x * b0.x, y1 = r2.y * b0.y, y2 = r2.z * b0.z, y3 = r2.w * b0.w;
            float y4 = r3.x * b1.x, y5 = r3.y * b1.y, y6 = r3.z * b1.z, y7 = r3.w * b1.w;
            if (npr < NPAIRS) { r2 = xn[1024 + 2 * t]; r3 = xn[1024 + 2 * t + 1]; }

            float a10 = y0 + y1, d10 = y0 - y1;
            float a11 = y2 + y3, d11 = y2 - y3;
            float a12 = y4 + y5, d12 = y4 - y5;
            float a13 = y6 + y7, d13 = y6 - y7;
            ((float4*)(Ab + 2048))[t] = make_float4(d10, d11, d12, d13);

            float a20 = a10 + a11, d20 = a10 - a11;
            float a21 = a12 + a13, d21 = a12 - a13;
            ((float2*)(Ab + 1024))[t] = make_float2(d20, d21);

            float a3v = a20 + a21;
            Ab[512 + t] = a20 - a21;

            float prt = __shfl_xor_sync(0xffffffffu, a3v, 1);
            if ((t & 1) == 0) {
                Ab[h]       = a3v + prt;
                Ab[256 + h] = a3v - prt;
            }
        }

        __syncthreads();   // the ONLY barrier per pair

        // ===== synthesis rows A and B: two independent gather trees ==========
        float4* oA = (float4*)(out + (size_t)(2 * pr) * DEPTHN);
        {
            // row A
            float a1A = Aa[p[0]] * g[0];
            a1A = fmaf(Aa[p[1]], g[1], a1A);
            float d2A = Aa[p[2]] * g[2];
            float a20A = a1A + d2A, a21A = a1A - d2A;
            float d3A = Aa[p[3]] * g[3];
            float d4A = Aa[p[4]] * g[4];
            float a30A = a20A + d3A, a31A = a20A - d3A;
            float a32A = a21A + d4A, a33A = a21A - d4A;
            float d5A = Aa[p[5]] * g[5];
            float d6A = Aa[p[6]] * g[6];
            float d7A = Aa[p[7]] * g[7];
            float d8A = Aa[p[8]] * g[8];

            // row B (independent chain — interleaves with A in the scheduler)
            float a1B = Ab[p[0]] * g[0];
            a1B = fmaf(Ab[p[1]], g[1], a1B);
            float d2B = Ab[p[2]] * g[2];
            float a20B = a1B + d2B, a21B = a1B - d2B;
            float d3B = Ab[p[3]] * g[3];
            float d4B = Ab[p[4]] * g[4];
            float a30B = a20B + d3B, a31B = a20B - d3B;
            float a32B = a21B + d4B, a33B = a21B - d4B;
            float d5B = Ab[p[5]] * g[5];
            float d6B = Ab[p[6]] * g[6];
            float d7B = Ab[p[7]] * g[7];
            float d8B = Ab[p[8]] * g[8];

            float4 o0, o1;
            o0.x = (a30A + d5A) * v0.x;
            o0.y = (a30A - d5A) * v0.y;
            o0.z = (a31A + d6A) * v0.z;
            o0.w = (a31A - d6A) * v0.w;
            o1.x = (a32A + d7A) * v1.x;
            o1.y = (a32A - d7A) * v1.y;
            o1.z = (a33A + d8A) * v1.z;
            o1.w = (a33A - d8A) * v1.w;
            oA[2 * t]     = o0;
            oA[2 * t + 1] = o1;

            o0.x = (a30B + d5B) * v0.x;
            o0.y = (a30B - d5B) * v0.y;
            o0.z = (a31B + d6B) * v0.z;
            o0.w = (a31B - d6B) * v0.w;
            o1.x = (a32B + d7B) * v1.x;
            o1.y = (a32B - d7B) * v1.y;
            o1.z = (a33B + d8B) * v1.z;
            o1.w = (a33B - d8B) * v1.w;
            oA[1024 + 2 * t]     = o0;
            oA[1024 + 2 * t + 1] = o1;
        }

        sel ^= 1;   // next pair writes the other buffer pair
    }
}

extern "C" void kernel_launch(void* const* d_in, const int* in_sizes, int n_in,
                              void* d_out, int out_size)
{
    const float* x    = (const float*)d_in[0];
    const float* vb   = (const float*)d_in[1];
    const float* vg   = (const float*)d_in[2];
    const float* vs   = (const float*)d_in[3];
    const int*   perm = (const int*)d_in[4];
    float*       out  = (float*)d_out;

    const size_t smem_bytes = 16384 * sizeof(float);   // 64 KB: 4 coeff buffers
    cudaFuncSetAttribute(wavelet_kernel,
                         cudaFuncAttributeMaxDynamicSharedMemorySize,
                         (int)smem_bytes);

    // 148 CTAs = 1/SM; each CTA sweeps ~27.7 row-PAIRS (4096 pairs total),
    // 1 barrier per pair, 2 independent row chains in flight per warp.
    wavelet_kernel<<<148, THREADS, smem_bytes>>>(x, vb, vg, vs, perm, out);
}